// round 2
// baseline (speedup 1.0000x reference)
#include <cuda_runtime.h>
#include <math.h>

#define Kc 3
#define Bc 512
#define Dc 1024
#define Hc 512
#define Cc 48
#define Tc 25
#define G4 2048
#define DP1 1025
#define FEATN 6288

// output section offsets (all float32, concatenated in tuple order)
#define O0 0                                  // labels_t   [T,B]
#define O1 (Tc*Bc)                            // probs      [B,T,C]
#define O2 (O1 + Bc*Tc*Cc)                    // curr_action[B,C]
#define O3 (O2 + Bc*Cc)                       // durations  [B,T+1]
#define O4 (O3 + Bc*(Tc+1))                   // att_t      [T,B,D]

// ---------------- scratch (device globals: no allocation allowed) ----------
__device__ float d_Y[Kc*Bc*Cc];       // per-TAB class probs
__device__ float d_feat[Bc*FEATN];
__device__ float d_x0[Bc*DP1];
__device__ float d_gx0[Bc*G4];        // x0 @ W_ih^T
__device__ float d_E[Cc*G4];          // embed @ W_ih[:, :D]^T
__device__ float d_P[Kc*Bc*Hc];       // S[k,b] @ Wattn^T
__device__ float d_sdur[Bc*Kc];
__device__ float d_gates[Bc*G4];      // h @ W_hh^T
__device__ float d_h[2][Bc*Hc];
__device__ float d_c[Bc*Hc];
__device__ int   d_labels[Bc];
__device__ float d_dur[Bc];
__device__ float d_WpT[Cc*Hc];        // Wp transposed
__device__ float d_wihdur[G4];        // W_ih[:, D]
__device__ float d_bsum[G4];          // b_ih + b_hh

// ---------------- generic tiled SGEMM:  C[m,n] = sum_k A[m,k] * B'[k,n] ----
// BT=true : B is [N,K] row-major (NT form, B'[k,n] = B[n*ldb+k])
// BT=false: B is [K,N] row-major (NN form)
// ACC: C += result ; bias: per-column bias (nullptr ok)
template<bool BT, bool ACC>
__global__ void __launch_bounds__(256)
sgemm(const float* __restrict__ A, const float* __restrict__ Bm,
      float* __restrict__ C, int M, int N, int K,
      int lda, int ldb, int ldc, const float* __restrict__ bias)
{
    __shared__ __align__(16) float As[16][68];
    __shared__ __align__(16) float Bs[16][68];
    const int tid = threadIdx.x;
    const int m0 = blockIdx.y * 64, n0 = blockIdx.x * 64;
    const int tx = tid & 15, ty = tid >> 4;
    const int lk = tid & 15, lm = tid >> 4;     // A / NT-B load map
    const int lnn = tid & 63, lkk = tid >> 6;   // NN-B load map
    float acc[4][4] = {};

    for (int k0 = 0; k0 < K; k0 += 16) {
#pragma unroll
        for (int i = 0; i < 4; i++) {
            int m = lm + i*16;
            float v = 0.f;
            if (m0+m < M && k0+lk < K) v = A[(size_t)(m0+m)*lda + k0+lk];
            As[lk][m] = v;
        }
        if (BT) {
#pragma unroll
            for (int i = 0; i < 4; i++) {
                int n = lm + i*16;
                float v = 0.f;
                if (n0+n < N && k0+lk < K) v = Bm[(size_t)(n0+n)*ldb + k0+lk];
                Bs[lk][n] = v;
            }
        } else {
#pragma unroll
            for (int i = 0; i < 4; i++) {
                int k = lkk + i*4;
                float v = 0.f;
                if (k0+k < K && n0+lnn < N) v = Bm[(size_t)(k0+k)*ldb + n0+lnn];
                Bs[k][lnn] = v;
            }
        }
        __syncthreads();
#pragma unroll
        for (int kk = 0; kk < 16; kk++) {
            float4 av = *reinterpret_cast<const float4*>(&As[kk][ty*4]);
            float4 bv = *reinterpret_cast<const float4*>(&Bs[kk][tx*4]);
            float a[4] = {av.x, av.y, av.z, av.w};
            float b[4] = {bv.x, bv.y, bv.z, bv.w};
#pragma unroll
            for (int i = 0; i < 4; i++)
#pragma unroll
                for (int j = 0; j < 4; j++)
                    acc[i][j] = fmaf(a[i], b[j], acc[i][j]);
        }
        __syncthreads();
    }
#pragma unroll
    for (int i = 0; i < 4; i++) {
        int m = m0 + ty*4 + i; if (m >= M) continue;
#pragma unroll
        for (int j = 0; j < 4; j++) {
            int n = n0 + tx*4 + j; if (n >= N) continue;
            float v = acc[i][j];
            if (bias) v += bias[n];
            if (ACC)  v += C[(size_t)m*ldc + n];
            C[(size_t)m*ldc + n] = v;
        }
    }
}

// ---------------- misc small kernels ---------------------------------------
__global__ void zero_state()
{
    int i = blockIdx.x * blockDim.x + threadIdx.x;
    if (i < Bc*Hc) { d_h[0][i] = 0.f; d_c[i] = 0.f; }
}

__global__ void precompute_small(const float* __restrict__ W_ih,
                                 const float* __restrict__ b_ih,
                                 const float* __restrict__ b_hh,
                                 const float* __restrict__ Wp)
{
    for (int i = blockIdx.x * blockDim.x + threadIdx.x; i < Cc*Hc;
         i += gridDim.x * blockDim.x) {
        int c = i >> 9, h = i & 511;
        d_WpT[i] = Wp[h*Cc + c];
        if (i < G4) {
            d_wihdur[i] = W_ih[(size_t)i*DP1 + Dc];
            d_bsum[i]   = b_ih[i] + b_hh[i];
        }
    }
}

// softmax over C=48 in place on d_Y rows; one warp per (k,b)
__global__ void cls_softmax()
{
    float* row = d_Y + (size_t)blockIdx.x * Cc;
    int lane = threadIdx.x;
    float v1 = row[lane];
    float v2 = (lane + 32 < Cc) ? row[lane + 32] : -3.4e38f;
    float m = fmaxf(v1, v2);
    for (int o = 16; o; o >>= 1) m = fmaxf(m, __shfl_xor_sync(0xffffffffu, m, o));
    float e1 = expf(v1 - m);
    float e2 = (lane + 32 < Cc) ? expf(v2 - m) : 0.f;
    float s = e1 + e2;
    for (int o = 16; o; o >>= 1) s += __shfl_xor_sync(0xffffffffu, s, o);
    float inv = 1.f / s;
    row[lane] = e1 * inv;
    if (lane + 32 < Cc) row[lane + 32] = e2 * inv;
}

// feat assembly + curr_action + curr_dur + sdur ; one block per b
__global__ void prep_kernel(const float* __restrict__ S, const float* __restrict__ R,
                            const float* __restrict__ dur_W, const float* __restrict__ dur_b,
                            const float* __restrict__ Wdur, float* __restrict__ out)
{
    __shared__ float red[256];
    const int b = blockIdx.x, tid = threadIdx.x;
    float* fr = d_feat + (size_t)b * FEATN;
    for (int i = tid; i < Kc*Cc; i += 256) {
        int k = i / Cc, c = i - k*Cc;
        fr[i] = d_Y[((size_t)k*Bc + b)*Cc + c];
    }
    for (int i = tid; i < Kc*Dc; i += 256) {
        int k = i >> 10, d = i & 1023;
        fr[Kc*Cc + i]         = S[((size_t)k*Bc + b)*Dc + d];
        fr[Kc*Cc + Kc*Dc + i] = R[((size_t)k*Bc + b)*Dc + d];
    }
    for (int i = tid; i < Cc; i += 256)
        out[O2 + (size_t)b*Cc + i] = d_Y[(size_t)b*Cc + i]
                                   + d_Y[((size_t)Bc + b)*Cc + i]
                                   + d_Y[((size_t)2*Bc + b)*Cc + i];
    // curr_dur = Rf . dur_W + dur_b
    float pd = 0.f;
    for (int i = tid; i < Kc*Dc; i += 256) {
        int k = i >> 10, d = i & 1023;
        pd += R[((size_t)k*Bc + b)*Dc + d] * dur_W[i];
    }
    red[tid] = pd; __syncthreads();
    for (int s = 128; s > 0; s >>= 1) { if (tid < s) red[tid] += red[tid + s]; __syncthreads(); }
    if (tid == 0) out[O3 + (size_t)b*(Tc+1)] = red[0] + dur_b[0];
    __syncthreads();
    // sdur[b][k] = S[k,b,:] . Wdur[:D]
    for (int k = 0; k < Kc; k++) {
        float ps = 0.f;
        for (int d = tid; d < Dc; d += 256)
            ps += S[((size_t)k*Bc + b)*Dc + d] * Wdur[d];
        red[tid] = ps; __syncthreads();
        for (int s = 128; s > 0; s >>= 1) { if (tid < s) red[tid] += red[tid + s]; __syncthreads(); }
        if (tid == 0) d_sdur[b*Kc + k] = red[0];
        __syncthreads();
    }
}

// fused per-step kernel: LSTM elementwise + logits/probs/argmax + attention +
// dur ; one block per b, 512 threads (16 warps)
__global__ void __launch_bounds__(512)
step_kernel(const float* __restrict__ S, const float* __restrict__ bp,
            const float* __restrict__ Wdur, const float* __restrict__ bdur,
            float* __restrict__ out, int t, int sel)
{
    __shared__ float sh[Hc];
    __shared__ float slog[Cc];
    __shared__ float sscore[3];
    __shared__ float saw[3];
    __shared__ float sred[16];
    const int b  = blockIdx.x;
    const int th = threadIdx.x;
    const int wid = th >> 5, lane = th & 31;
    const float* h_in = d_h[sel];
    float* h_out = d_h[sel ^ 1];

    // ---- phase 1: gates -> (h,c), hdur partial ----
    float g[4];
    if (t == 0) {
#pragma unroll
        for (int j = 0; j < 4; j++) {
            int gi = j*Hc + th;
            g[j] = d_gx0[(size_t)b*G4 + gi] + d_bsum[gi];
        }
    } else {
        int lab = d_labels[b];
        float dp = d_dur[b];
#pragma unroll
        for (int j = 0; j < 4; j++) {
            int gi = j*Hc + th;
            g[j] = d_gates[(size_t)b*G4 + gi] + d_E[(size_t)lab*G4 + gi]
                 + dp * d_wihdur[gi] + d_bsum[gi];
        }
    }
    float ig = 1.f / (1.f + expf(-g[0]));
    float fg = 1.f / (1.f + expf(-g[1]));
    float gg = tanhf(g[2]);
    float og = 1.f / (1.f + expf(-g[3]));
    int idx = b*Hc + th;
    float cn = fg * d_c[idx] + ig * gg;
    d_c[idx] = cn;
    float hn = og * tanhf(cn);
    h_out[idx] = hn;
    sh[th] = hn;
    // hdur uses h_{t-1}
    float hp = h_in[idx] * Wdur[Dc + th];
    for (int o = 16; o; o >>= 1) hp += __shfl_xor_sync(0xffffffffu, hp, o);
    if (lane == 0) sred[wid] = hp;
    __syncthreads();

    // ---- phase 2: logits (warp per class, 3 each) + attn scores ----
    for (int cc = wid; cc < Cc; cc += 16) {
        float s = 0.f;
        const float* wr = d_WpT + (size_t)cc*Hc;
        for (int j = lane; j < Hc; j += 32) s += sh[j] * wr[j];
        for (int o = 16; o; o >>= 1) s += __shfl_xor_sync(0xffffffffu, s, o);
        if (lane == 0) slog[cc] = s + bp[cc];
    }
    if (wid < 3) {
        float s = 0.f;
        const float* Pr = d_P + ((size_t)wid*Bc + b)*Hc;
        for (int j = lane; j < Hc; j += 32) s += sh[j] * Pr[j];
        for (int o = 16; o; o >>= 1) s += __shfl_xor_sync(0xffffffffu, s, o);
        if (lane == 0) sscore[wid] = s * 0.03125f;  // 1/sqrt(1024)
    }
    __syncthreads();

    // ---- phase 3: softmax/argmax over 48, aw softmax over 3, dur ----
    if (wid == 0) {
        float v1 = slog[lane];
        float v2 = (lane < Cc - 32) ? slog[32 + lane] : -3.4e38f;
        float m = fmaxf(v1, v2);
        for (int o = 16; o; o >>= 1) m = fmaxf(m, __shfl_xor_sync(0xffffffffu, m, o));
        float e1 = expf(v1 - m);
        float e2 = (lane < Cc - 32) ? expf(v2 - m) : 0.f;
        float s = e1 + e2;
        for (int o = 16; o; o >>= 1) s += __shfl_xor_sync(0xffffffffu, s, o);
        float inv = 1.f / s;
        size_t pb = O1 + ((size_t)b*Tc + t)*Cc;
        out[pb + lane] = e1 * inv;
        if (lane < Cc - 32) out[pb + 32 + lane] = e2 * inv;
        // argmax with first-occurrence tie-break
        float bv; int bi;
        if (lane < Cc - 32 && v2 > v1) { bv = v2; bi = 32 + lane; }
        else                           { bv = v1; bi = lane; }
        for (int o = 16; o; o >>= 1) {
            float ov = __shfl_xor_sync(0xffffffffu, bv, o);
            int   oi = __shfl_xor_sync(0xffffffffu, bi, o);
            if (ov > bv || (ov == bv && oi < bi)) { bv = ov; bi = oi; }
        }
        // hdur total (sred[0..15])
        float hv = (lane < 16) ? sred[lane] : 0.f;
        for (int o = 8; o; o >>= 1) hv += __shfl_xor_sync(0xffffffffu, hv, o);
        if (lane == 0) {
            out[O0 + (size_t)t*Bc + b] = (float)bi;
            d_labels[b] = bi;
            float s0 = sscore[0], s1 = sscore[1], s2 = sscore[2];
            float sm = fmaxf(s0, fmaxf(s1, s2));
            float a0 = expf(s0 - sm), a1 = expf(s1 - sm), a2 = expf(s2 - sm);
            float z = 1.f / (a0 + a1 + a2);
            a0 *= z; a1 *= z; a2 *= z;
            saw[0] = a0; saw[1] = a1; saw[2] = a2;
            float dur = a0*d_sdur[b*Kc] + a1*d_sdur[b*Kc+1] + a2*d_sdur[b*Kc+2]
                      + hv + bdur[0];
            out[O3 + (size_t)b*(Tc+1) + t + 1] = dur;
            d_dur[b] = dur;
        }
    }
    __syncthreads();

    // ---- phase 4: att output ----
    float a0 = saw[0], a1 = saw[1], a2 = saw[2];
    size_t ab = O4 + ((size_t)t*Bc + b)*Dc;
    const float* S0 = S + (size_t)b*Dc;
    const float* S1 = S + ((size_t)Bc + b)*Dc;
    const float* S2 = S + ((size_t)2*Bc + b)*Dc;
    for (int d = th; d < Dc; d += 512)
        out[ab + d] = a0*S0[d] + a1*S1[d] + a2*S2[d];
}

// ---------------- host ------------------------------------------------------
extern "C" void kernel_launch(void* const* d_in, const int* in_sizes, int n_in,
                              void* d_out, int out_size)
{
    const float* S     = (const float*)d_in[0];
    const float* R     = (const float*)d_in[1];
    const float* cls_W = (const float*)d_in[2];
    const float* cls_b = (const float*)d_in[3];
    const float* dur_W = (const float*)d_in[4];
    const float* dur_b = (const float*)d_in[5];
    const float* lin_W = (const float*)d_in[6];
    const float* lin_b = (const float*)d_in[7];
    const float* W_ih  = (const float*)d_in[8];
    const float* W_hh  = (const float*)d_in[9];
    const float* b_ih  = (const float*)d_in[10];
    const float* b_hh  = (const float*)d_in[11];
    const float* Wp    = (const float*)d_in[12];
    const float* bp    = (const float*)d_in[13];
    const float* Wdur  = (const float*)d_in[14];
    const float* bdur  = (const float*)d_in[15];
    const float* embed = (const float*)d_in[16];
    const float* Wattn = (const float*)d_in[17];
    float* out = (float*)d_out;

    float *pY, *pfeat, *px0, *pgx0, *pE, *pP, *pgates, *ph;
    cudaGetSymbolAddress((void**)&pY,     d_Y);
    cudaGetSymbolAddress((void**)&pfeat,  d_feat);
    cudaGetSymbolAddress((void**)&px0,    d_x0);
    cudaGetSymbolAddress((void**)&pgx0,   d_gx0);
    cudaGetSymbolAddress((void**)&pE,     d_E);
    cudaGetSymbolAddress((void**)&pP,     d_P);
    cudaGetSymbolAddress((void**)&pgates, d_gates);
    cudaGetSymbolAddress((void**)&ph,     d_h);

    zero_state<<<(Bc*Hc + 511)/512, 512>>>();
    precompute_small<<<48, 512>>>(W_ih, b_ih, b_hh, Wp);

    // per-TAB classifier logits: Y_k = S_k @ clsW_k[:D] + R_k @ clsW_k[D:] + b
    for (int k = 0; k < Kc; k++) {
        sgemm<false, false><<<dim3(1, 8), 256>>>(
            S + (size_t)k*Bc*Dc, cls_W + (size_t)k*2*Dc*Cc,
            pY + (size_t)k*Bc*Cc, Bc, Cc, Dc, Dc, Cc, Cc, cls_b + k*Cc);
        sgemm<false, true><<<dim3(1, 8), 256>>>(
            R + (size_t)k*Bc*Dc, cls_W + ((size_t)k*2*Dc + Dc)*Cc,
            pY + (size_t)k*Bc*Cc, Bc, Cc, Dc, Dc, Cc, Cc, nullptr);
    }
    cls_softmax<<<Kc*Bc, 32>>>();
    prep_kernel<<<Bc, 256>>>(S, R, dur_W, dur_b, Wdur, out);

    // x0 = feat @ lin_W + lin_b                 [512 x 1025, K=6288]
    sgemm<false, false><<<dim3(17, 8), 256>>>(
        pfeat, lin_W, px0, Bc, DP1, FEATN, FEATN, DP1, DP1, lin_b);
    // gx0 = x0 @ W_ih^T                         [512 x 2048, K=1025]
    sgemm<true, false><<<dim3(32, 8), 256>>>(
        px0, W_ih, pgx0, Bc, G4, DP1, DP1, DP1, G4, nullptr);
    // E = embed @ W_ih[:, :D]^T                 [48 x 2048, K=1024]
    sgemm<true, false><<<dim3(32, 1), 256>>>(
        embed, W_ih, pE, Cc, G4, Dc, Dc, DP1, G4, nullptr);
    // P_k = S_k @ Wattn^T                       [512 x 512, K=1024] x3
    for (int k = 0; k < Kc; k++)
        sgemm<true, false><<<dim3(8, 8), 256>>>(
            S + (size_t)k*Bc*Dc, Wattn, pP + (size_t)k*Bc*Hc,
            Bc, Hc, Dc, Dc, Dc, Hc, nullptr);

    int sel = 0;
    for (int t = 0; t < Tc; t++) {
        if (t > 0)
            sgemm<true, false><<<dim3(32, 8), 256>>>(
                ph + (size_t)sel*Bc*Hc, W_hh, pgates,
                Bc, G4, Hc, Hc, Hc, G4, nullptr);
        step_kernel<<<Bc, 512>>>(S, bp, Wdur, bdur, out, t, sel);
        sel ^= 1;
    }
}

// round 3
// speedup vs baseline: 1.2302x; 1.2302x over previous
#include <cuda_runtime.h>
#include <math.h>

#define Kc 3
#define Bc 512
#define Dc 1024
#define Hc 512
#define Cc 48
#define Tc 25
#define G4 2048
#define DP1 1025
#define FEATN 6288

// output section offsets (all float32, concatenated in tuple order)
#define O0 0                                  // labels_t   [T,B]
#define O1 (Tc*Bc)                            // probs      [B,T,C]
#define O2 (O1 + Bc*Tc*Cc)                    // curr_action[B,C]
#define O3 (O2 + Bc*Cc)                       // durations  [B,T+1]
#define O4 (O3 + Bc*(Tc+1))                   // att_t      [T,B,D]

// ---------------- scratch (device globals: no allocation allowed) ----------
__device__ float d_Y[Kc*Bc*Cc];       // per-TAB class probs (post-softmax)
__device__ float d_feat[Bc*FEATN];
__device__ float d_x0[Bc*DP1];
__device__ float d_gx0[Bc*G4];        // x0 @ W_ih^T + bsum
__device__ float d_E[Cc*G4];          // embed @ W_ih[:, :D]^T
__device__ float d_P[Kc*Bc*Hc];       // S[k,b] @ Wattn^T
__device__ float d_sdur[Bc*Kc];
__device__ float d_gates[Bc*G4];      // h @ W_hh^T + bsum
__device__ float d_h[2][Bc*Hc];
__device__ float d_c[Bc*Hc];
__device__ int   d_labels[Bc];
__device__ float d_dur[Bc];
__device__ float d_WpT[Cc*Hc];        // Wp transposed
__device__ float d_wihdur[G4];        // W_ih[:, D]
__device__ float d_bsum[G4];          // b_ih + b_hh

// ---------------- packed f32x2 helpers --------------------------------------
typedef unsigned long long ull;

__device__ __forceinline__ ull pk(float lo, float hi) {
    ull r; asm("mov.b64 %0, {%1,%2};" : "=l"(r) : "f"(lo), "f"(hi)); return r;
}
__device__ __forceinline__ void fma2(ull &d, ull a, ull b) {
    asm("fma.rn.f32x2 %0, %1, %2, %0;" : "+l"(d) : "l"(a), "l"(b));
}
__device__ __forceinline__ float2 upk(ull v) {
    float2 r; asm("mov.b64 {%0,%1}, %2;" : "=f"(r.x), "=f"(r.y) : "l"(v)); return r;
}

// ---------------- tiled SGEMM with packed fp32 FMA --------------------------
// C[m,n] = sum_k A[m,k]*B'[k,n] (+bias[n]).  Tile TM x 128, 256 threads.
// BT=true : B is [N,K] row-major (B'[k,n] = B[n*ldb+k]);  BT=false: B is [K,N].
// Batched over blockIdx.z with strides sA,sB,sC (elements).
template<int TM, bool BT>
__global__ void __launch_bounds__(256)
gemm2(const float* __restrict__ A, const float* __restrict__ Bm,
      float* __restrict__ C, int M, int N, int K,
      int lda, int ldb, int ldc, const float* __restrict__ bias,
      long long sA, long long sB, long long sC)
{
    constexpr int MM = TM / 16;                 // rows per thread (4 or 2)
    __shared__ __align__(16) float As[16][TM + 4];
    __shared__ __align__(16) float Bs[16][132];

    A  += (size_t)blockIdx.z * sA;
    Bm += (size_t)blockIdx.z * sB;
    C  += (size_t)blockIdx.z * sC;

    const int tid = threadIdx.x;
    const int m0 = blockIdx.y * TM, n0 = blockIdx.x * 128;
    const int tx = tid & 15, ty = tid >> 4;
    const int lk = tid & 15, lm = tid >> 4;
    const int lnn = tid & 127, lkk = tid >> 7;

    ull acc[MM][4];
#pragma unroll
    for (int i = 0; i < MM; i++)
#pragma unroll
        for (int j = 0; j < 4; j++) acc[i][j] = 0ull;

    for (int k0 = 0; k0 < K; k0 += 16) {
#pragma unroll
        for (int i = 0; i < MM; i++) {
            int m = lm + i*16;
            float v = 0.f;
            if (m0 + m < M && k0 + lk < K) v = A[(size_t)(m0+m)*lda + k0 + lk];
            As[lk][m] = v;
        }
        if (BT) {
#pragma unroll
            for (int i = 0; i < 8; i++) {
                int n = lm + i*16;
                float v = 0.f;
                if (n0 + n < N && k0 + lk < K) v = Bm[(size_t)(n0+n)*ldb + k0 + lk];
                Bs[lk][n] = v;
            }
        } else {
#pragma unroll
            for (int i = 0; i < 8; i++) {
                int k = lkk + i*2;
                float v = 0.f;
                if (k0 + k < K && n0 + lnn < N) v = Bm[(size_t)(k0+k)*ldb + n0 + lnn];
                Bs[k][lnn] = v;
            }
        }
        __syncthreads();
#pragma unroll
        for (int kk = 0; kk < 16; kk++) {
            float4 bv0 = *reinterpret_cast<const float4*>(&Bs[kk][tx*4]);
            float4 bv1 = *reinterpret_cast<const float4*>(&Bs[kk][64 + tx*4]);
            ull b0 = pk(bv0.x, bv0.y), b1 = pk(bv0.z, bv0.w);
            ull b2 = pk(bv1.x, bv1.y), b3 = pk(bv1.z, bv1.w);
            if (MM == 4) {
                float4 av = *reinterpret_cast<const float4*>(&As[kk][ty*4]);
                float a4[4] = {av.x, av.y, av.z, av.w};
#pragma unroll
                for (int i = 0; i < 4; i++) {
                    ull a2 = pk(a4[i], a4[i]);
                    fma2(acc[i][0], a2, b0);
                    fma2(acc[i][1], a2, b1);
                    fma2(acc[i][2], a2, b2);
                    fma2(acc[i][3], a2, b3);
                }
            } else {
                float2 av = *reinterpret_cast<const float2*>(&As[kk][ty*2]);
                float a4[2] = {av.x, av.y};
#pragma unroll
                for (int i = 0; i < MM; i++) {
                    ull a2 = pk(a4[i], a4[i]);
                    fma2(acc[i][0], a2, b0);
                    fma2(acc[i][1], a2, b1);
                    fma2(acc[i][2], a2, b2);
                    fma2(acc[i][3], a2, b3);
                }
            }
        }
        __syncthreads();
    }

#pragma unroll
    for (int i = 0; i < MM; i++) {
        int m = m0 + ty*MM + i;
        if (m >= M) continue;
        float* Cr = C + (size_t)m * ldc;
#pragma unroll
        for (int jp = 0; jp < 4; jp++) {
            float2 v = upk(acc[i][jp]);
            int nb = n0 + ((jp >= 2) ? 64 : 0) + tx*4 + (jp & 1)*2;
            if (nb < N)     Cr[nb]     = v.x + (bias ? bias[nb]     : 0.f);
            if (nb + 1 < N) Cr[nb + 1] = v.y + (bias ? bias[nb + 1] : 0.f);
        }
    }
}

// ---------------- init: zero state + small precomputes ----------------------
__global__ void init_kernel(const float* __restrict__ W_ih,
                            const float* __restrict__ b_ih,
                            const float* __restrict__ b_hh,
                            const float* __restrict__ Wp)
{
    for (int i = blockIdx.x*blockDim.x + threadIdx.x; i < Bc*Hc;
         i += gridDim.x*blockDim.x) {
        d_h[0][i] = 0.f; d_c[i] = 0.f;
        if (i < Cc*Hc) {
            int c = i >> 9, h = i & 511;
            d_WpT[i] = Wp[h*Cc + c];
        }
        if (i < G4) {
            d_wihdur[i] = W_ih[(size_t)i*DP1 + Dc];
            d_bsum[i]   = b_ih[i] + b_hh[i];
        }
    }
}

// ---------------- fused classifier: logits + softmax ------------------------
// grid (Bc/32, Kc); block computes rows b0..b0+31, all 48 classes.
// thread (rr = tid>>3, cs = tid&7) holds 6 cols: cs + 8*j.
__global__ void __launch_bounds__(256)
cls_kernel(const float* __restrict__ S, const float* __restrict__ R,
           const float* __restrict__ W, const float* __restrict__ bcls)
{
    __shared__ __align__(16) float As[32][20];   // [row][kk]
    __shared__ __align__(16) float Bs[48][20];   // [c][kk]
    const int k  = blockIdx.y;
    const int b0 = blockIdx.x * 32;
    const int tid = threadIdx.x;
    const int rr = tid >> 3, cs = tid & 7;
    float acc[6] = {};

    for (int ph = 0; ph < 2; ph++) {
        const float* Ap = (ph ? R : S) + ((size_t)k*Bc + b0)*Dc;
        const float* Wb = W + ((size_t)k*2*Dc + (size_t)ph*Dc)*Cc;
        for (int k0 = 0; k0 < Dc; k0 += 16) {
            {   int lk = tid & 15, lr = tid >> 4;
                As[lr][lk]      = Ap[(size_t)lr*Dc + k0 + lk];
                As[lr + 16][lk] = Ap[(size_t)(lr + 16)*Dc + k0 + lk];
            }
#pragma unroll
            for (int j = 0; j < 3; j++) {
                int idx = tid + j*256;
                int c = idx >> 4, kk = idx & 15;
                Bs[c][kk] = Wb[(size_t)(k0 + kk)*Cc + c];
            }
            __syncthreads();
#pragma unroll
            for (int kq = 0; kq < 4; kq++) {
                float4 a = *reinterpret_cast<const float4*>(&As[rr][kq*4]);
#pragma unroll
                for (int j = 0; j < 6; j++) {
                    float4 b = *reinterpret_cast<const float4*>(&Bs[cs + 8*j][kq*4]);
                    acc[j] = fmaf(a.x, b.x, acc[j]);
                    acc[j] = fmaf(a.y, b.y, acc[j]);
                    acc[j] = fmaf(a.z, b.z, acc[j]);
                    acc[j] = fmaf(a.w, b.w, acc[j]);
                }
            }
            __syncthreads();
        }
    }
    // bias + softmax across 8 threads (width-8 groups) x 6 vals each
    float mx = -3.4e38f;
#pragma unroll
    for (int j = 0; j < 6; j++) {
        acc[j] += bcls[k*Cc + cs + 8*j];
        mx = fmaxf(mx, acc[j]);
    }
    for (int o = 4; o; o >>= 1) mx = fmaxf(mx, __shfl_xor_sync(0xffffffffu, mx, o));
    float sum = 0.f;
#pragma unroll
    for (int j = 0; j < 6; j++) { acc[j] = expf(acc[j] - mx); sum += acc[j]; }
    for (int o = 4; o; o >>= 1) sum += __shfl_xor_sync(0xffffffffu, sum, o);
    float inv = 1.f / sum;
    float* Yr = d_Y + ((size_t)k*Bc + b0 + rr)*Cc;
#pragma unroll
    for (int j = 0; j < 6; j++) Yr[cs + 8*j] = acc[j] * inv;
}

// feat assembly + curr_action + curr_dur + sdur ; one block per b
__global__ void prep_kernel(const float* __restrict__ S, const float* __restrict__ R,
                            const float* __restrict__ dur_W, const float* __restrict__ dur_b,
                            const float* __restrict__ Wdur, float* __restrict__ out)
{
    __shared__ float red[256];
    const int b = blockIdx.x, tid = threadIdx.x;
    float* fr = d_feat + (size_t)b * FEATN;
    for (int i = tid; i < Kc*Cc; i += 256) {
        int k = i / Cc, c = i - k*Cc;
        fr[i] = d_Y[((size_t)k*Bc + b)*Cc + c];
    }
    for (int i = tid; i < Kc*Dc; i += 256) {
        int k = i >> 10, d = i & 1023;
        fr[Kc*Cc + i]         = S[((size_t)k*Bc + b)*Dc + d];
        fr[Kc*Cc + Kc*Dc + i] = R[((size_t)k*Bc + b)*Dc + d];
    }
    for (int i = tid; i < Cc; i += 256)
        out[O2 + (size_t)b*Cc + i] = d_Y[(size_t)b*Cc + i]
                                   + d_Y[((size_t)Bc + b)*Cc + i]
                                   + d_Y[((size_t)2*Bc + b)*Cc + i];
    float pd = 0.f;
    for (int i = tid; i < Kc*Dc; i += 256) {
        int k = i >> 10, d = i & 1023;
        pd += R[((size_t)k*Bc + b)*Dc + d] * dur_W[i];
    }
    red[tid] = pd; __syncthreads();
    for (int s = 128; s > 0; s >>= 1) { if (tid < s) red[tid] += red[tid + s]; __syncthreads(); }
    if (tid == 0) out[O3 + (size_t)b*(Tc+1)] = red[0] + dur_b[0];
    __syncthreads();
    for (int k = 0; k < Kc; k++) {
        float ps = 0.f;
        for (int d = tid; d < Dc; d += 256)
            ps += S[((size_t)k*Bc + b)*Dc + d] * Wdur[d];
        red[tid] = ps; __syncthreads();
        for (int s = 128; s > 0; s >>= 1) { if (tid < s) red[tid] += red[tid + s]; __syncthreads(); }
        if (tid == 0) d_sdur[b*Kc + k] = red[0];
        __syncthreads();
    }
}

// fused per-step kernel: LSTM elementwise + logits/probs/argmax + attention +
// dur ; one block per b, 512 threads (16 warps). bsum already folded in GEMMs.
__global__ void __launch_bounds__(512)
step_kernel(const float* __restrict__ S, const float* __restrict__ bp,
            const float* __restrict__ Wdur, const float* __restrict__ bdur,
            float* __restrict__ out, int t, int sel)
{
    __shared__ float sh[Hc];
    __shared__ float slog[Cc];
    __shared__ float sscore[3];
    __shared__ float saw[3];
    __shared__ float sred[16];
    const int b  = blockIdx.x;
    const int th = threadIdx.x;
    const int wid = th >> 5, lane = th & 31;
    const float* h_in = d_h[sel];
    float* h_out = d_h[sel ^ 1];

    float g[4];
    if (t == 0) {
#pragma unroll
        for (int j = 0; j < 4; j++) g[j] = d_gx0[(size_t)b*G4 + j*Hc + th];
    } else {
        int lab = d_labels[b];
        float dp = d_dur[b];
#pragma unroll
        for (int j = 0; j < 4; j++) {
            int gi = j*Hc + th;
            g[j] = d_gates[(size_t)b*G4 + gi] + d_E[(size_t)lab*G4 + gi]
                 + dp * d_wihdur[gi];
        }
    }
    float ig = 1.f / (1.f + expf(-g[0]));
    float fg = 1.f / (1.f + expf(-g[1]));
    float gg = tanhf(g[2]);
    float og = 1.f / (1.f + expf(-g[3]));
    int idx = b*Hc + th;
    float cn = fg * d_c[idx] + ig * gg;
    d_c[idx] = cn;
    float hn = og * tanhf(cn);
    h_out[idx] = hn;
    sh[th] = hn;
    float hp = h_in[idx] * Wdur[Dc + th];
    for (int o = 16; o; o >>= 1) hp += __shfl_xor_sync(0xffffffffu, hp, o);
    if (lane == 0) sred[wid] = hp;
    __syncthreads();

    for (int cc = wid; cc < Cc; cc += 16) {
        float s = 0.f;
        const float* wr = d_WpT + (size_t)cc*Hc;
        for (int j = lane; j < Hc; j += 32) s += sh[j] * wr[j];
        for (int o = 16; o; o >>= 1) s += __shfl_xor_sync(0xffffffffu, s, o);
        if (lane == 0) slog[cc] = s + bp[cc];
    }
    if (wid < 3) {
        float s = 0.f;
        const float* Pr = d_P + ((size_t)wid*Bc + b)*Hc;
        for (int j = lane; j < Hc; j += 32) s += sh[j] * Pr[j];
        for (int o = 16; o; o >>= 1) s += __shfl_xor_sync(0xffffffffu, s, o);
        if (lane == 0) sscore[wid] = s * 0.03125f;  // 1/sqrt(1024)
    }
    __syncthreads();

    if (wid == 0) {
        float v1 = slog[lane];
        float v2 = (lane < Cc - 32) ? slog[32 + lane] : -3.4e38f;
        float m = fmaxf(v1, v2);
        for (int o = 16; o; o >>= 1) m = fmaxf(m, __shfl_xor_sync(0xffffffffu, m, o));
        float e1 = expf(v1 - m);
        float e2 = (lane < Cc - 32) ? expf(v2 - m) : 0.f;
        float s = e1 + e2;
        for (int o = 16; o; o >>= 1) s += __shfl_xor_sync(0xffffffffu, s, o);
        float inv = 1.f / s;
        size_t pb = O1 + ((size_t)b*Tc + t)*Cc;
        out[pb + lane] = e1 * inv;
        if (lane < Cc - 32) out[pb + 32 + lane] = e2 * inv;
        float bv; int bi;
        if (lane < Cc - 32 && v2 > v1) { bv = v2; bi = 32 + lane; }
        else                           { bv = v1; bi = lane; }
        for (int o = 16; o; o >>= 1) {
            float ov = __shfl_xor_sync(0xffffffffu, bv, o);
            int   oi = __shfl_xor_sync(0xffffffffu, bi, o);
            if (ov > bv || (ov == bv && oi < bi)) { bv = ov; bi = oi; }
        }
        float hv = (lane < 16) ? sred[lane] : 0.f;
        for (int o = 8; o; o >>= 1) hv += __shfl_xor_sync(0xffffffffu, hv, o);
        if (lane == 0) {
            out[O0 + (size_t)t*Bc + b] = (float)bi;
            d_labels[b] = bi;
            float s0 = sscore[0], s1 = sscore[1], s2 = sscore[2];
            float sm = fmaxf(s0, fmaxf(s1, s2));
            float a0 = expf(s0 - sm), a1 = expf(s1 - sm), a2 = expf(s2 - sm);
            float z = 1.f / (a0 + a1 + a2);
            a0 *= z; a1 *= z; a2 *= z;
            saw[0] = a0; saw[1] = a1; saw[2] = a2;
            float dur = a0*d_sdur[b*Kc] + a1*d_sdur[b*Kc+1] + a2*d_sdur[b*Kc+2]
                      + hv + bdur[0];
            out[O3 + (size_t)b*(Tc+1) + t + 1] = dur;
            d_dur[b] = dur;
        }
    }
    __syncthreads();

    float a0 = saw[0], a1 = saw[1], a2 = saw[2];
    size_t ab = O4 + ((size_t)t*Bc + b)*Dc;
    const float* S0 = S + (size_t)b*Dc;
    const float* S1 = S + ((size_t)Bc + b)*Dc;
    const float* S2 = S + ((size_t)2*Bc + b)*Dc;
    for (int d = th; d < Dc; d += 512)
        out[ab + d] = a0*S0[d] + a1*S1[d] + a2*S2[d];
}

// ---------------- host ------------------------------------------------------
extern "C" void kernel_launch(void* const* d_in, const int* in_sizes, int n_in,
                              void* d_out, int out_size)
{
    const float* S     = (const float*)d_in[0];
    const float* R     = (const float*)d_in[1];
    const float* cls_W = (const float*)d_in[2];
    const float* cls_b = (const float*)d_in[3];
    const float* dur_W = (const float*)d_in[4];
    const float* dur_b = (const float*)d_in[5];
    const float* lin_W = (const float*)d_in[6];
    const float* lin_b = (const float*)d_in[7];
    const float* W_ih  = (const float*)d_in[8];
    const float* W_hh  = (const float*)d_in[9];
    const float* b_ih  = (const float*)d_in[10];
    const float* b_hh  = (const float*)d_in[11];
    const float* Wp    = (const float*)d_in[12];
    const float* bp    = (const float*)d_in[13];
    const float* Wdur  = (const float*)d_in[14];
    const float* bdur  = (const float*)d_in[15];
    const float* embed = (const float*)d_in[16];
    const float* Wattn = (const float*)d_in[17];
    float* out = (float*)d_out;

    float *pfeat, *px0, *pgx0, *pE, *pP, *pgates, *ph, *pbsum;
    cudaGetSymbolAddress((void**)&pfeat,  d_feat);
    cudaGetSymbolAddress((void**)&px0,    d_x0);
    cudaGetSymbolAddress((void**)&pgx0,   d_gx0);
    cudaGetSymbolAddress((void**)&pE,     d_E);
    cudaGetSymbolAddress((void**)&pP,     d_P);
    cudaGetSymbolAddress((void**)&pgates, d_gates);
    cudaGetSymbolAddress((void**)&ph,     d_h);
    cudaGetSymbolAddress((void**)&pbsum,  d_bsum);

    init_kernel<<<256, 512>>>(W_ih, b_ih, b_hh, Wp);

    // fused per-TAB classifier (logits + softmax)
    cls_kernel<<<dim3(Bc/32, Kc), 256>>>(S, R, cls_W, cls_b);
    prep_kernel<<<Bc, 256>>>(S, R, dur_W, dur_b, Wdur, out);

    // x0 = feat @ lin_W + lin_b                 [512 x 1025, K=6288]
    gemm2<32, false><<<dim3(9, 16), 256>>>(
        pfeat, lin_W, px0, Bc, DP1, FEATN, FEATN, DP1, DP1, lin_b, 0, 0, 0);
    // gx0 = x0 @ W_ih^T + bsum                  [512 x 2048, K=1025]
    gemm2<64, true><<<dim3(16, 8), 256>>>(
        px0, W_ih, pgx0, Bc, G4, DP1, DP1, DP1, G4, pbsum, 0, 0, 0);
    // E = embed @ W_ih[:, :D]^T                 [48 x 2048, K=1024]
    gemm2<32, true><<<dim3(16, 2), 256>>>(
        embed, W_ih, pE, Cc, G4, Dc, Dc, DP1, G4, nullptr, 0, 0, 0);
    // P_k = S_k @ Wattn^T                       [512 x 512, K=1024] batched x3
    gemm2<64, true><<<dim3(4, 8, 3), 256>>>(
        S, Wattn, pP, Bc, Hc, Dc, Dc, Dc, Hc, nullptr,
        (long long)Bc*Dc, 0, (long long)Bc*Hc);

    int sel = 0;
    for (int t = 0; t < Tc; t++) {
        if (t > 0)
            gemm2<64, true><<<dim3(16, 8), 256>>>(
                ph + (size_t)sel*Bc*Hc, W_hh, pgates,
                Bc, G4, Hc, Hc, Hc, G4, pbsum, 0, 0, 0);
        step_kernel<<<Bc, 512>>>(S, bp, Wdur, bdur, out, t, sel);
        sel ^= 1;
    }
}